// round 8
// baseline (speedup 1.0000x reference)
#include <cuda_runtime.h>
#include <cuda_bf16.h>
#include <cstdint>

// Problem constants (B=1 fixed)
#define S_LEN   2048
#define HID     6144
#define QKV_OUT 6400   // HID + 2*128
#define NH      48
#define HD      128

// Scratch (no cudaMalloc allowed)
__device__ float g_qkv [S_LEN * QKV_OUT];
__device__ float g_attn[S_LEN * HID];

// ---------------------------------------------------------------------------
// helpers
// ---------------------------------------------------------------------------
__device__ __forceinline__ uint32_t smem_u32(const void* p) {
    uint32_t a;
    asm("{ .reg .u64 t; cvta.to.shared.u64 t, %1; cvt.u32.u64 %0, t; }"
        : "=r"(a) : "l"(p));
    return a;
}

__device__ __forceinline__ void mma_bf16(float* d, const uint32_t* a, const uint32_t* b) {
    asm volatile(
        "mma.sync.aligned.m16n8k16.row.col.f32.bf16.bf16.f32 "
        "{%0,%1,%2,%3}, {%4,%5,%6,%7}, {%8,%9}, {%0,%1,%2,%3};"
        : "+f"(d[0]), "+f"(d[1]), "+f"(d[2]), "+f"(d[3])
        : "r"(a[0]), "r"(a[1]), "r"(a[2]), "r"(a[3]), "r"(b[0]), "r"(b[1]));
}

__device__ __forceinline__ void ldsm_x4(uint32_t* r, uint32_t addr) {
    asm volatile("ldmatrix.sync.aligned.m8n8.x4.shared.b16 {%0,%1,%2,%3}, [%4];"
                 : "=r"(r[0]), "=r"(r[1]), "=r"(r[2]), "=r"(r[3]) : "r"(addr));
}
__device__ __forceinline__ void ldsm_x2(uint32_t* r, uint32_t addr) {
    asm volatile("ldmatrix.sync.aligned.m8n8.x2.shared.b16 {%0,%1}, [%2];"
                 : "=r"(r[0]), "=r"(r[1]) : "r"(addr));
}
__device__ __forceinline__ void ldsm_x2_t(uint32_t& r0, uint32_t& r1, uint32_t addr) {
    asm volatile("ldmatrix.sync.aligned.m8n8.x2.trans.shared.b16 {%0,%1}, [%2];"
                 : "=r"(r0), "=r"(r1) : "r"(addr));
}

// split two floats into bf16 hi pair + bf16 lo (residual) pair
__device__ __forceinline__ void pack_split2(float x, float y, uint32_t& hi, uint32_t& lo) {
    __nv_bfloat162 h = __floats2bfloat162_rn(x, y);
    float2 hf = __bfloat1622float2(h);
    __nv_bfloat162 l = __floats2bfloat162_rn(x - hf.x, y - hf.y);
    hi = *reinterpret_cast<uint32_t*>(&h);
    lo = *reinterpret_cast<uint32_t*>(&l);
}

// load 16 consecutive floats, split, store 8 hi u32 at hi[], 8 lo u32 at lo[]
__device__ __forceinline__ void split16(const float* src, uint32_t* hi, uint32_t* lo,
                                        float scale) {
    #pragma unroll
    for (int i = 0; i < 4; i++) {
        float4 f = *(const float4*)(src + i * 4);
        f.x *= scale; f.y *= scale; f.z *= scale; f.w *= scale;
        uint32_t h0, l0, h1, l1;
        pack_split2(f.x, f.y, h0, l0);
        pack_split2(f.z, f.w, h1, l1);
        hi[i * 2] = h0; hi[i * 2 + 1] = h1;
        lo[i * 2] = l0; lo[i * 2 + 1] = l1;
    }
}

// ---------------------------------------------------------------------------
// bf16-split GEMM: C[M,N] = A[M,K] * B[N,K]^T + bias[N]
// CTA 128x128, BK=32, 256 threads, 8 warps (2x4), warp tile 64x32.
// Row pitch 44 u32 (176B): 16 hi | 16 lo | 12 pad. ldsm phases conflict-free
// (11r mod 8 covers all groups). 2 CTAs/SM.
// ---------------------------------------------------------------------------
#define GP3   44
#define GTILE (128 * GP3)      // 5632 u32 per tile
#define GSTG  (2 * GTILE)      // A + B per stage

__global__ void __launch_bounds__(256, 2) gemm_bf16s(
    const float* __restrict__ A, const float* __restrict__ B,
    const float* __restrict__ bias, float* __restrict__ C,
    int M, int N, int K)
{
    extern __shared__ uint32_t gsm[];
    const uint32_t smb = smem_u32(gsm);

    const int tid = threadIdx.x;
    const int wid = tid >> 5, lid = tid & 31;
    const int g   = lid >> 2;
    const int t4  = lid & 3;
    const int wr  = wid >> 2;       // 0..1 (M)
    const int wc  = wid & 3;        // 0..3 (N)

    const int bm = blockIdx.y * 128, bn = blockIdx.x * 128;

    // loaders: 2 threads per row, each 16 consecutive floats
    const int lr   = tid >> 1;
    const int half = tid & 1;
    const float* Ag = A + (long)(bm + lr) * K + half * 16;
    const float* Bg = B + (long)(bn + lr) * K + half * 16;
    const uint32_t sto = (uint32_t)(lr * GP3 + half * 8);

    // ldmatrix lane base addresses (bytes within a tile)
    const uint32_t a_row = (uint32_t)(((wr * 64 + (lid & 15)) * GP3 + (lid >> 4) * 4) * 4);
    const uint32_t b_row = (uint32_t)(((wc * 32 + (lid & 7)) * GP3 + ((lid >> 3) & 1) * 4) * 4);

    float acc[4][4][4];
    #pragma unroll
    for (int i = 0; i < 4; i++)
        #pragma unroll
        for (int j = 0; j < 4; j++)
            #pragma unroll
            for (int k = 0; k < 4; k++) acc[i][j][k] = 0.0f;

    const int NS = K >> 5;   // stages of K=32
    float4 ar[4], br[4];

    // prologue: stage 0
    #pragma unroll
    for (int i = 0; i < 4; i++) {
        ar[i] = *(const float4*)(Ag + i * 4);
        br[i] = *(const float4*)(Bg + i * 4);
    }
    {
        uint32_t hi[8], lo[8];
        split16((const float*)ar, hi, lo, 1.0f);
        *(uint4*)(gsm + sto)          = *(uint4*)(hi);
        *(uint4*)(gsm + sto + 4)      = *(uint4*)(hi + 4);
        *(uint4*)(gsm + sto + 16)     = *(uint4*)(lo);
        *(uint4*)(gsm + sto + 20)     = *(uint4*)(lo + 4);
        split16((const float*)br, hi, lo, 1.0f);
        *(uint4*)(gsm + GTILE + sto)      = *(uint4*)(hi);
        *(uint4*)(gsm + GTILE + sto + 4)  = *(uint4*)(hi + 4);
        *(uint4*)(gsm + GTILE + sto + 16) = *(uint4*)(lo);
        *(uint4*)(gsm + GTILE + sto + 20) = *(uint4*)(lo + 4);
    }
    __syncthreads();

    for (int s = 0; s < NS; s++) {
        if (s + 1 < NS) {
            const long koff = 32L * (s + 1);
            #pragma unroll
            for (int i = 0; i < 4; i++) {
                ar[i] = *(const float4*)(Ag + koff + i * 4);
                br[i] = *(const float4*)(Bg + koff + i * 4);
            }
        }

        // compute on slot s&1: two k16 steps
        {
            const uint32_t abase = smb + (uint32_t)((s & 1) * GSTG) * 4u + a_row;
            const uint32_t bbase = smb + (uint32_t)((s & 1) * GSTG + GTILE) * 4u + b_row;

            #pragma unroll
            for (int ks = 0; ks < 2; ks++) {
                const uint32_t ao = abase + ks * 32;   // +8 u32 per k-step
                const uint32_t bo = bbase + ks * 32;

                uint32_t ah[4][4], al[4][4];
                #pragma unroll
                for (int mt = 0; mt < 4; mt++) {
                    ldsm_x4(ah[mt], ao + mt * (16 * GP3 * 4));
                    ldsm_x4(al[mt], ao + mt * (16 * GP3 * 4) + 64);
                }
                #pragma unroll
                for (int nt = 0; nt < 4; nt++) {
                    uint32_t bh[2], bl[2];
                    ldsm_x2(bh, bo + nt * (8 * GP3 * 4));
                    ldsm_x2(bl, bo + nt * (8 * GP3 * 4) + 64);
                    #pragma unroll
                    for (int mt = 0; mt < 4; mt++) {
                        mma_bf16(acc[mt][nt], ah[mt], bh);
                        mma_bf16(acc[mt][nt], ah[mt], bl);
                        mma_bf16(acc[mt][nt], al[mt], bh);
                    }
                }
            }
        }

        if (s + 1 < NS) {
            uint32_t* dst = gsm + ((s + 1) & 1) * GSTG;
            uint32_t hi[8], lo[8];
            split16((const float*)ar, hi, lo, 1.0f);
            *(uint4*)(dst + sto)          = *(uint4*)(hi);
            *(uint4*)(dst + sto + 4)      = *(uint4*)(hi + 4);
            *(uint4*)(dst + sto + 16)     = *(uint4*)(lo);
            *(uint4*)(dst + sto + 20)     = *(uint4*)(lo + 4);
            split16((const float*)br, hi, lo, 1.0f);
            *(uint4*)(dst + GTILE + sto)      = *(uint4*)(hi);
            *(uint4*)(dst + GTILE + sto + 4)  = *(uint4*)(hi + 4);
            *(uint4*)(dst + GTILE + sto + 16) = *(uint4*)(lo);
            *(uint4*)(dst + GTILE + sto + 20) = *(uint4*)(lo + 4);
            __syncthreads();
        }
    }

    // epilogue
    #pragma unroll
    for (int mt = 0; mt < 4; mt++) {
        const int row = bm + wr * 64 + mt * 16 + g;
        #pragma unroll
        for (int nt = 0; nt < 4; nt++) {
            const int col = bn + wc * 32 + nt * 8 + t4 * 2;
            const float b0 = bias[col], b1 = bias[col + 1];
            float2 lo, hi;
            lo.x = acc[mt][nt][0] + b0; lo.y = acc[mt][nt][1] + b1;
            hi.x = acc[mt][nt][2] + b0; hi.y = acc[mt][nt][3] + b1;
            *(float2*)&C[(long)row * N + col]       = lo;
            *(float2*)&C[(long)(row + 8) * N + col] = hi;
        }
    }
}

// ---------------------------------------------------------------------------
// MQA causal flash attention, bf16-split HMMA.
// CTA: 256 threads (8 warps x m16), BQ=128, BKV=64, D=128.
// smem pitch 132 u32 per row: 64 hi pairs | 64 lo pairs | 4 pad.
// ---------------------------------------------------------------------------
#define QP 132

__global__ void __launch_bounds__(256) mqa_flash_hmma(
    const float* __restrict__ qkv, float* __restrict__ attn_out)
{
    extern __shared__ uint32_t asm_[];
    uint32_t* q_s = asm_;                 // [128][QP]
    uint32_t* k_s = q_s + 128 * QP;       // [64][QP]
    uint32_t* v_s = k_s + 64 * QP;        // [64][QP]

    const int h  = blockIdx.y;
    const int bq = blockIdx.x;
    const int q0 = bq * 128;
    const int tid = threadIdx.x;
    const int wid = tid >> 5, lid = tid & 31;
    const int g = lid >> 2, t4 = lid & 3;

    const uint32_t v_base = smem_u32(v_s);

    // Q loader: 2 threads per row (128 rows), 4 chunks of 16 floats each
    {
        const int lr  = tid >> 1;
        const int lc0 = (tid & 1) * 16;
        const float* src = qkv + (long)(q0 + lr) * QKV_OUT + h * HD;
        uint32_t* dst = q_s + lr * QP;
        #pragma unroll
        for (int jj = 0; jj < 4; jj++) {
            const int c16 = lc0 + 32 * jj;
            split16(src + c16, dst + (c16 >> 1), dst + (c16 >> 1) + 64,
                    0.08838834764831845f);
        }
    }

    float o[16][4];
    #pragma unroll
    for (int i = 0; i < 16; i++)
        #pragma unroll
        for (int j = 0; j < 4; j++) o[i][j] = 0.0f;
    float m0 = -1e30f, m1 = -1e30f, l0 = 0.0f, l1 = 0.0f;

    const int row0 = q0 + wid * 16 + g;
    const int row1 = row0 + 8;
    const int wrow_max = q0 + wid * 16 + 15;

    const int kt_end = 2 * bq + 1;   // kv tiles of 64 covering causal range
    for (int kt = 0; kt <= kt_end; kt++) {
        __syncthreads();   // Q ready / previous-iter smem reads done
        {
            // K/V loader: 4 threads per row (64 rows), 2 chunks of 16 each
            const int lr  = tid >> 2;
            const int lc0 = (tid & 3) * 16;
            const float* kp = qkv + (long)(kt * 64 + lr) * QKV_OUT + HID;
            uint32_t* kd = k_s + lr * QP;
            uint32_t* vd = v_s + lr * QP;
            #pragma unroll
            for (int jj = 0; jj < 2; jj++) {
                const int c16 = lc0 + 64 * jj;
                split16(kp + c16,      kd + (c16 >> 1), kd + (c16 >> 1) + 64, 1.0f);
                split16(kp + HD + c16, vd + (c16 >> 1), vd + (c16 >> 1) + 64, 1.0f);
            }
        }
        __syncthreads();

        // warps whose rows are entirely above this kv tile skip compute
        if (kt * 64 > wrow_max) continue;

        // ---- S = Q K^T (3-term bf16) ----
        float s[8][4];
        #pragma unroll
        for (int nt = 0; nt < 8; nt++)
            #pragma unroll
            for (int j = 0; j < 4; j++) s[nt][j] = 0.0f;

        const uint32_t* qb = q_s + (wid * 16) * QP;
        #pragma unroll
        for (int ks = 0; ks < 8; ks++) {
            uint32_t ah[4], al[4];
            const int ro = g * QP + ks * 8 + t4;
            ah[0] = qb[ro];          ah[1] = qb[ro + 8 * QP];
            ah[2] = qb[ro + 4];      ah[3] = qb[ro + 8 * QP + 4];
            al[0] = qb[ro + 64];     al[1] = qb[ro + 8 * QP + 64];
            al[2] = qb[ro + 68];     al[3] = qb[ro + 8 * QP + 68];
            #pragma unroll
            for (int nt = 0; nt < 8; nt++) {
                const int rb = (nt * 8 + g) * QP + ks * 8 + t4;
                uint32_t bh[2] = { k_s[rb],      k_s[rb + 4]  };
                uint32_t bl[2] = { k_s[rb + 64], k_s[rb + 68] };
                mma_bf16(s[nt], ah, bh);
                mma_bf16(s[nt], ah, bl);
                mma_bf16(s[nt], al, bh);
            }
        }

        // causal mask (only tiles straddling the diagonal need it)
        if (kt * 64 + 63 > row0) {
            #pragma unroll
            for (int nt = 0; nt < 8; nt++) {
                const int col = kt * 64 + nt * 8 + 2 * t4;
                if (col     > row0) s[nt][0] = -1e30f;
                if (col + 1 > row0) s[nt][1] = -1e30f;
                if (col     > row1) s[nt][2] = -1e30f;
                if (col + 1 > row1) s[nt][3] = -1e30f;
            }
        }

        // ---- online softmax (rows g and g+8) ----
        float mt0 = -1e30f, mt1 = -1e30f;
        #pragma unroll
        for (int nt = 0; nt < 8; nt++) {
            mt0 = fmaxf(mt0, fmaxf(s[nt][0], s[nt][1]));
            mt1 = fmaxf(mt1, fmaxf(s[nt][2], s[nt][3]));
        }
        mt0 = fmaxf(mt0, __shfl_xor_sync(0xffffffffu, mt0, 1));
        mt0 = fmaxf(mt0, __shfl_xor_sync(0xffffffffu, mt0, 2));
        mt1 = fmaxf(mt1, __shfl_xor_sync(0xffffffffu, mt1, 1));
        mt1 = fmaxf(mt1, __shfl_xor_sync(0xffffffffu, mt1, 2));

        const float mn0 = fmaxf(m0, mt0), mn1 = fmaxf(m1, mt1);
        const float al0 = __expf(m0 - mn0), al1 = __expf(m1 - mn1);

        float ps0 = 0.0f, ps1 = 0.0f;
        #pragma unroll
        for (int nt = 0; nt < 8; nt++) {
            s[nt][0] = __expf(s[nt][0] - mn0);
            s[nt][1] = __expf(s[nt][1] - mn0);
            s[nt][2] = __expf(s[nt][2] - mn1);
            s[nt][3] = __expf(s[nt][3] - mn1);
            ps0 += s[nt][0] + s[nt][1];
            ps1 += s[nt][2] + s[nt][3];
        }
        ps0 += __shfl_xor_sync(0xffffffffu, ps0, 1);
        ps0 += __shfl_xor_sync(0xffffffffu, ps0, 2);
        ps1 += __shfl_xor_sync(0xffffffffu, ps1, 1);
        ps1 += __shfl_xor_sync(0xffffffffu, ps1, 2);
        l0 = l0 * al0 + ps0; m0 = mn0;
        l1 = l1 * al1 + ps1; m1 = mn1;

        #pragma unroll
        for (int nt = 0; nt < 16; nt++) {
            o[nt][0] *= al0; o[nt][1] *= al0;
            o[nt][2] *= al1; o[nt][3] *= al1;
        }

        // ---- O += P V (3-term bf16); P frags packed directly from S frags ----
        #pragma unroll
        for (int jj = 0; jj < 4; jj++) {
            uint32_t ph[4], pl[4];
            pack_split2(s[2*jj][0],   s[2*jj][1],   ph[0], pl[0]);
            pack_split2(s[2*jj][2],   s[2*jj][3],   ph[1], pl[1]);
            pack_split2(s[2*jj+1][0], s[2*jj+1][1], ph[2], pl[2]);
            pack_split2(s[2*jj+1][2], s[2*jj+1][3], ph[3], pl[3]);

            const uint32_t rowaddr = v_base + (uint32_t)(((jj * 16 + (lid & 15)) * QP) * 4);
            #pragma unroll
            for (int nt = 0; nt < 16; nt++) {
                uint32_t bh[2], bl[2];
                ldsm_x2_t(bh[0], bh[1], rowaddr + nt * 16);
                ldsm_x2_t(bl[0], bl[1], rowaddr + 256 + nt * 16);
                mma_bf16(o[nt], ph, bh);
                mma_bf16(o[nt], ph, bl);
                mma_bf16(o[nt], pl, bh);
            }
        }
    }

    // epilogue
    const float i0 = 1.0f / l0, i1 = 1.0f / l1;
    #pragma unroll
    for (int nt = 0; nt < 16; nt++) {
        const int d = nt * 8 + 2 * t4;
        float2 a, b;
        a.x = o[nt][0] * i0; a.y = o[nt][1] * i0;
        b.x = o[nt][2] * i1; b.y = o[nt][3] * i1;
        *(float2*)&attn_out[(long)row0 * HID + h * HD + d] = a;
        *(float2*)&attn_out[(long)row1 * HID + h * HD + d] = b;
    }
}

// ---------------------------------------------------------------------------
extern "C" void kernel_launch(void* const* d_in, const int* in_sizes, int n_in,
                              void* d_out, int out_size)
{
    const float* x    = (const float*)d_in[0];
    const float* wqkv = (const float*)d_in[1];
    const float* bqkv = (const float*)d_in[2];
    const float* wo   = (const float*)d_in[3];
    const float* bo   = (const float*)d_in[4];
    float* out = (float*)d_out;

    float *qkv_buf, *attn_buf;
    cudaGetSymbolAddress((void**)&qkv_buf,  g_qkv);
    cudaGetSymbolAddress((void**)&attn_buf, g_attn);

    const int gemm_smem = 2 * GSTG * sizeof(uint32_t);     // 90112
    cudaFuncSetAttribute(gemm_bf16s,
                         cudaFuncAttributeMaxDynamicSharedMemorySize, gemm_smem);

    const int attn_smem = (128 + 64 + 64) * QP * sizeof(uint32_t);  // 135168
    cudaFuncSetAttribute(mqa_flash_hmma,
                         cudaFuncAttributeMaxDynamicSharedMemorySize, attn_smem);

    // 1) QKV projection
    {
        dim3 grid(QKV_OUT / 128, S_LEN / 128);
        gemm_bf16s<<<grid, 256, gemm_smem>>>(x, wqkv, bqkv, qkv_buf,
                                             S_LEN, QKV_OUT, HID);
    }
    // 2) attention
    {
        dim3 grid(S_LEN / 128, NH);
        mqa_flash_hmma<<<grid, 256, attn_smem>>>(qkv_buf, attn_buf);
    }
    // 3) output projection
    {
        dim3 grid(HID / 128, S_LEN / 128);
        gemm_bf16s<<<grid, 256, gemm_smem>>>(attn_buf, wo, bo, out,
                                             S_LEN, HID, HID);
    }
}

// round 9
// speedup vs baseline: 1.1874x; 1.1874x over previous
#include <cuda_runtime.h>
#include <cuda_bf16.h>
#include <cuda_fp16.h>
#include <cstdint>

// Problem constants (B=1 fixed)
#define S_LEN   2048
#define HID     6144
#define QKV_OUT 6400   // HID + 2*128
#define NH      48
#define HD      128

// Scratch (no cudaMalloc allowed)
__device__ float g_qkv [S_LEN * QKV_OUT];
__device__ float g_attn[S_LEN * HID];

// ---------------------------------------------------------------------------
// helpers
// ---------------------------------------------------------------------------
__device__ __forceinline__ uint32_t smem_u32(const void* p) {
    uint32_t a;
    asm("{ .reg .u64 t; cvta.to.shared.u64 t, %1; cvt.u32.u64 %0, t; }"
        : "=r"(a) : "l"(p));
    return a;
}

__device__ __forceinline__ void mma_bf16(float* d, const uint32_t* a, const uint32_t* b) {
    asm volatile(
        "mma.sync.aligned.m16n8k16.row.col.f32.bf16.bf16.f32 "
        "{%0,%1,%2,%3}, {%4,%5,%6,%7}, {%8,%9}, {%0,%1,%2,%3};"
        : "+f"(d[0]), "+f"(d[1]), "+f"(d[2]), "+f"(d[3])
        : "r"(a[0]), "r"(a[1]), "r"(a[2]), "r"(a[3]), "r"(b[0]), "r"(b[1]));
}

__device__ __forceinline__ void mma_f16(float* d, const uint32_t* a, const uint32_t* b) {
    asm volatile(
        "mma.sync.aligned.m16n8k16.row.col.f32.f16.f16.f32 "
        "{%0,%1,%2,%3}, {%4,%5,%6,%7}, {%8,%9}, {%0,%1,%2,%3};"
        : "+f"(d[0]), "+f"(d[1]), "+f"(d[2]), "+f"(d[3])
        : "r"(a[0]), "r"(a[1]), "r"(a[2]), "r"(a[3]), "r"(b[0]), "r"(b[1]));
}

__device__ __forceinline__ void ldsm_x4(uint32_t* r, uint32_t addr) {
    asm volatile("ldmatrix.sync.aligned.m8n8.x4.shared.b16 {%0,%1,%2,%3}, [%4];"
                 : "=r"(r[0]), "=r"(r[1]), "=r"(r[2]), "=r"(r[3]) : "r"(addr));
}
__device__ __forceinline__ void ldsm_x2(uint32_t* r, uint32_t addr) {
    asm volatile("ldmatrix.sync.aligned.m8n8.x2.shared.b16 {%0,%1}, [%2];"
                 : "=r"(r[0]), "=r"(r[1]) : "r"(addr));
}
__device__ __forceinline__ void ldsm_x2_t(uint32_t& r0, uint32_t& r1, uint32_t addr) {
    asm volatile("ldmatrix.sync.aligned.m8n8.x2.trans.shared.b16 {%0,%1}, [%2];"
                 : "=r"(r0), "=r"(r1) : "r"(addr));
}

// ---- bf16 split helpers (attention) ----
__device__ __forceinline__ void pack_split2(float x, float y, uint32_t& hi, uint32_t& lo) {
    __nv_bfloat162 h = __floats2bfloat162_rn(x, y);
    float2 hf = __bfloat1622float2(h);
    __nv_bfloat162 l = __floats2bfloat162_rn(x - hf.x, y - hf.y);
    hi = *reinterpret_cast<uint32_t*>(&h);
    lo = *reinterpret_cast<uint32_t*>(&l);
}

__device__ __forceinline__ void split16(const float* src, uint32_t* hi, uint32_t* lo,
                                        float scale) {
    #pragma unroll
    for (int i = 0; i < 4; i++) {
        float4 f = *(const float4*)(src + i * 4);
        f.x *= scale; f.y *= scale; f.z *= scale; f.w *= scale;
        uint32_t h0, l0, h1, l1;
        pack_split2(f.x, f.y, h0, l0);
        pack_split2(f.z, f.w, h1, l1);
        hi[i * 2] = h0; hi[i * 2 + 1] = h1;
        lo[i * 2] = l0; lo[i * 2 + 1] = l1;
    }
}

// ---- fp16 helpers (GEMM) ----
__device__ __forceinline__ void pack_split2h(float x, float y, uint32_t& hi, uint32_t& lo) {
    __half2 h = __floats2half2_rn(x, y);
    float2 hf = __half22float2(h);
    __half2 l = __floats2half2_rn(x - hf.x, y - hf.y);
    hi = *reinterpret_cast<uint32_t*>(&h);
    lo = *reinterpret_cast<uint32_t*>(&l);
}

// split 8 floats -> 4 hi u32 + 4 lo u32 (fp16)
__device__ __forceinline__ void split8h(const float4& f0, const float4& f1,
                                        uint32_t* hi, uint32_t* lo) {
    pack_split2h(f0.x, f0.y, hi[0], lo[0]);
    pack_split2h(f0.z, f0.w, hi[1], lo[1]);
    pack_split2h(f1.x, f1.y, hi[2], lo[2]);
    pack_split2h(f1.z, f1.w, hi[3], lo[3]);
}

// round 8 floats -> 4 hi u32 (fp16, no residual)
__device__ __forceinline__ void round8h(const float4& f0, const float4& f1, uint32_t* hi) {
    __half2 h0 = __floats2half2_rn(f0.x, f0.y);
    __half2 h1 = __floats2half2_rn(f0.z, f0.w);
    __half2 h2 = __floats2half2_rn(f1.x, f1.y);
    __half2 h3 = __floats2half2_rn(f1.z, f1.w);
    hi[0] = *reinterpret_cast<uint32_t*>(&h0);
    hi[1] = *reinterpret_cast<uint32_t*>(&h1);
    hi[2] = *reinterpret_cast<uint32_t*>(&h2);
    hi[3] = *reinterpret_cast<uint32_t*>(&h3);
}

// ---------------------------------------------------------------------------
// fp16 2-term GEMM: C[M,N] = A[M,K] * B[N,K]^T + bias[N]
// A split exactly into fp16 hi+lo (2 MMAs: ah*bh + al*bh); B fp16 hi only.
// CTA 128x128, BK=16, 256 threads, 8 warps (2x4), warp tile 64x32, 2 CTAs/SM.
// A pitch 20 u32 {8 hi | 8 lo | 4 pad}; B pitch 12 u32 {8 hi | 4 pad}.
// Bank stagger: A 5r mod 8, B 3r mod 8 -> all ldsm phases conflict-free.
// ---------------------------------------------------------------------------
#define GPA   20
#define GPB   12
#define GTA   (128 * GPA)          // 2560 u32
#define GTB   (128 * GPB)          // 1536 u32
#define GSTG  (GTA + GTB)          // 4096 u32 per stage

__global__ void __launch_bounds__(256, 2) gemm_f16s(
    const float* __restrict__ A, const float* __restrict__ B,
    const float* __restrict__ bias, float* __restrict__ C,
    int M, int N, int K)
{
    extern __shared__ uint32_t gsm[];
    const uint32_t smb = smem_u32(gsm);

    const int tid = threadIdx.x;
    const int wid = tid >> 5, lid = tid & 31;
    const int g   = lid >> 2;
    const int t4  = lid & 3;
    const int wr  = wid >> 2;       // 0..1
    const int wc  = wid & 3;        // 0..3

    const int bm = blockIdx.y * 128, bn = blockIdx.x * 128;

    // loaders: 2 threads per row, each 8 consecutive floats
    const int lr   = tid >> 1;
    const int half = tid & 1;
    const float* Ag = A + (long)(bm + lr) * K + half * 8;
    const float* Bg = B + (long)(bn + lr) * K + half * 8;
    const uint32_t stoA = (uint32_t)(lr * GPA + half * 4);
    const uint32_t stoB = (uint32_t)(lr * GPB + half * 4);

    // ldmatrix lane addresses (bytes within a tile)
    const uint32_t a_row = (uint32_t)(((wr * 64 + (lid & 15)) * GPA + (lid >> 4) * 4) * 4);
    const uint32_t b_row = (uint32_t)(((wc * 32 + (lid & 7)) * GPB + ((lid >> 3) & 1) * 4) * 4);

    float acc[4][4][4];
    #pragma unroll
    for (int i = 0; i < 4; i++)
        #pragma unroll
        for (int j = 0; j < 4; j++)
            #pragma unroll
            for (int k = 0; k < 4; k++) acc[i][j][k] = 0.0f;

    const int NS = K >> 4;
    float4 ar0, ar1, br0, br1;

    // prologue: stage 0
    ar0 = *(const float4*)(Ag);     ar1 = *(const float4*)(Ag + 4);
    br0 = *(const float4*)(Bg);     br1 = *(const float4*)(Bg + 4);
    {
        uint32_t hi[4], lo[4];
        split8h(ar0, ar1, hi, lo);
        *(uint4*)(gsm + stoA)     = *(uint4*)hi;
        *(uint4*)(gsm + stoA + 8) = *(uint4*)lo;
        round8h(br0, br1, hi);
        *(uint4*)(gsm + GTA + stoB) = *(uint4*)hi;
    }
    __syncthreads();

    for (int s = 0; s < NS; s++) {
        if (s + 1 < NS) {
            const long koff = 16L * (s + 1);
            ar0 = *(const float4*)(Ag + koff);  ar1 = *(const float4*)(Ag + koff + 4);
            br0 = *(const float4*)(Bg + koff);  br1 = *(const float4*)(Bg + koff + 4);
        }

        // compute on slot s&1
        {
            const uint32_t abase = smb + (uint32_t)((s & 1) * GSTG) * 4u + a_row;
            const uint32_t bbase = smb + (uint32_t)((s & 1) * GSTG + GTA) * 4u + b_row;

            uint32_t ah[4][4], al[4][4];
            #pragma unroll
            for (int mt = 0; mt < 4; mt++) {
                ldsm_x4(ah[mt], abase + mt * (16 * GPA * 4));
                ldsm_x4(al[mt], abase + mt * (16 * GPA * 4) + 32);
            }
            #pragma unroll
            for (int nt = 0; nt < 4; nt++) {
                uint32_t bh[2];
                ldsm_x2(bh, bbase + nt * (8 * GPB * 4));
                #pragma unroll
                for (int mt = 0; mt < 4; mt++) mma_f16(acc[mt][nt], ah[mt], bh);
                #pragma unroll
                for (int mt = 0; mt < 4; mt++) mma_f16(acc[mt][nt], al[mt], bh);
            }
        }

        if (s + 1 < NS) {
            uint32_t* dst = gsm + ((s + 1) & 1) * GSTG;
            uint32_t hi[4], lo[4];
            split8h(ar0, ar1, hi, lo);
            *(uint4*)(dst + stoA)     = *(uint4*)hi;
            *(uint4*)(dst + stoA + 8) = *(uint4*)lo;
            round8h(br0, br1, hi);
            *(uint4*)(dst + GTA + stoB) = *(uint4*)hi;
            __syncthreads();
        }
    }

    // epilogue
    #pragma unroll
    for (int mt = 0; mt < 4; mt++) {
        const int row = bm + wr * 64 + mt * 16 + g;
        #pragma unroll
        for (int nt = 0; nt < 4; nt++) {
            const int col = bn + wc * 32 + nt * 8 + t4 * 2;
            const float b0 = bias[col], b1 = bias[col + 1];
            float2 lo, hi;
            lo.x = acc[mt][nt][0] + b0; lo.y = acc[mt][nt][1] + b1;
            hi.x = acc[mt][nt][2] + b0; hi.y = acc[mt][nt][3] + b1;
            *(float2*)&C[(long)row * N + col]       = lo;
            *(float2*)&C[(long)(row + 8) * N + col] = hi;
        }
    }
}

// ---------------------------------------------------------------------------
// MQA causal flash attention, bf16-split HMMA (exact R6 version, measured best).
// CTA: 128 threads (4 warps x m16), BQ=64, BKV=64, D=128.
// ---------------------------------------------------------------------------
#define QP 132

__global__ void __launch_bounds__(128) mqa_flash_hmma(
    const float* __restrict__ qkv, float* __restrict__ attn_out)
{
    extern __shared__ uint32_t asm_[];
    uint32_t* q_s = asm_;                 // [64][QP]
    uint32_t* k_s = q_s + 64 * QP;
    uint32_t* v_s = k_s + 64 * QP;

    const int h  = blockIdx.y;
    const int bq = blockIdx.x;
    const int q0 = bq * 64;
    const int tid = threadIdx.x;
    const int wid = tid >> 5, lid = tid & 31;
    const int g = lid >> 2, t4 = lid & 3;

    const uint32_t v_base = smem_u32(v_s);

    const int lr  = tid >> 1;            // row 0..63
    const int lc0 = (tid & 1) * 16;      // chunk base 0 or 16

    // Load Q tile (pre-scaled by 1/sqrt(128)), split into hi/lo bf16.
    {
        const float* src = qkv + (long)(q0 + lr) * QKV_OUT + h * HD;
        uint32_t* dst = q_s + lr * QP;
        #pragma unroll
        for (int jj = 0; jj < 4; jj++) {
            const int c16 = lc0 + 32 * jj;
            split16(src + c16, dst + (c16 >> 1), dst + (c16 >> 1) + 64,
                    0.08838834764831845f);
        }
    }

    float o[16][4];
    #pragma unroll
    for (int i = 0; i < 16; i++)
        #pragma unroll
        for (int j = 0; j < 4; j++) o[i][j] = 0.0f;
    float m0 = -1e30f, m1 = -1e30f, l0 = 0.0f, l1 = 0.0f;

    const int row0 = q0 + wid * 16 + g;
    const int row1 = row0 + 8;

    for (int kt = 0; kt <= bq; kt++) {
        __syncthreads();
        {
            const float* kp = qkv + (long)(kt * 64 + lr) * QKV_OUT + HID;
            uint32_t* kd = k_s + lr * QP;
            uint32_t* vd = v_s + lr * QP;
            #pragma unroll
            for (int jj = 0; jj < 4; jj++) {
                const int c16 = lc0 + 32 * jj;
                split16(kp + c16,      kd + (c16 >> 1), kd + (c16 >> 1) + 64, 1.0f);
                split16(kp + HD + c16, vd + (c16 >> 1), vd + (c16 >> 1) + 64, 1.0f);
            }
        }
        __syncthreads();

        // ---- S = Q K^T (3-term bf16) ----
        float s[8][4];
        #pragma unroll
        for (int nt = 0; nt < 8; nt++)
            #pragma unroll
            for (int j = 0; j < 4; j++) s[nt][j] = 0.0f;

        const uint32_t* qb = q_s + (wid * 16) * QP;
        #pragma unroll
        for (int ks = 0; ks < 8; ks++) {
            uint32_t ah[4], al[4];
            const int ro = g * QP + ks * 8 + t4;
            ah[0] = qb[ro];          ah[1] = qb[ro + 8 * QP];
            ah[2] = qb[ro + 4];      ah[3] = qb[ro + 8 * QP + 4];
            al[0] = qb[ro + 64];     al[1] = qb[ro + 8 * QP + 64];
            al[2] = qb[ro + 68];     al[3] = qb[ro + 8 * QP + 68];
            #pragma unroll
            for (int nt = 0; nt < 8; nt++) {
                const int rb = (nt * 8 + g) * QP + ks * 8 + t4;
                uint32_t bh[2] = { k_s[rb],      k_s[rb + 4]  };
                uint32_t bl[2] = { k_s[rb + 64], k_s[rb + 68] };
                mma_bf16(s[nt], ah, bh);
                mma_bf16(s[nt], ah, bl);
                mma_bf16(s[nt], al, bh);
            }
        }

        if (kt == bq) {
            #pragma unroll
            for (int nt = 0; nt < 8; nt++) {
                const int col = kt * 64 + nt * 8 + 2 * t4;
                if (col     > row0) s[nt][0] = -1e30f;
                if (col + 1 > row0) s[nt][1] = -1e30f;
                if (col     > row1) s[nt][2] = -1e30f;
                if (col + 1 > row1) s[nt][3] = -1e30f;
            }
        }

        float mt0 = -1e30f, mt1 = -1e30f;
        #pragma unroll
        for (int nt = 0; nt < 8; nt++) {
            mt0 = fmaxf(mt0, fmaxf(s[nt][0], s[nt][1]));
            mt1 = fmaxf(mt1, fmaxf(s[nt][2], s[nt][3]));
        }
        mt0 = fmaxf(mt0, __shfl_xor_sync(0xffffffffu, mt0, 1));
        mt0 = fmaxf(mt0, __shfl_xor_sync(0xffffffffu, mt0, 2));
        mt1 = fmaxf(mt1, __shfl_xor_sync(0xffffffffu, mt1, 1));
        mt1 = fmaxf(mt1, __shfl_xor_sync(0xffffffffu, mt1, 2));

        const float mn0 = fmaxf(m0, mt0), mn1 = fmaxf(m1, mt1);
        const float al0 = __expf(m0 - mn0), al1 = __expf(m1 - mn1);

        float ps0 = 0.0f, ps1 = 0.0f;
        #pragma unroll
        for (int nt = 0; nt < 8; nt++) {
            s[nt][0] = __expf(s[nt][0] - mn0);
            s[nt][1] = __expf(s[nt][1] - mn0);
            s[nt][2] = __expf(s[nt][2] - mn1);
            s[nt][3] = __expf(s[nt][3] - mn1);
            ps0 += s[nt][0] + s[nt][1];
            ps1 += s[nt][2] + s[nt][3];
        }
        ps0 += __shfl_xor_sync(0xffffffffu, ps0, 1);
        ps0 += __shfl_xor_sync(0xffffffffu, ps0, 2);
        ps1 += __shfl_xor_sync(0xffffffffu, ps1, 1);
        ps1 += __shfl_xor_sync(0xffffffffu, ps1, 2);
        l0 = l0 * al0 + ps0; m0 = mn0;
        l1 = l1 * al1 + ps1; m1 = mn1;

        #pragma unroll
        for (int nt = 0; nt < 16; nt++) {
            o[nt][0] *= al0; o[nt][1] *= al0;
            o[nt][2] *= al1; o[nt][3] *= al1;
        }

        #pragma unroll
        for (int jj = 0; jj < 4; jj++) {
            uint32_t ph[4], pl[4];
            pack_split2(s[2*jj][0],   s[2*jj][1],   ph[0], pl[0]);
            pack_split2(s[2*jj][2],   s[2*jj][3],   ph[1], pl[1]);
            pack_split2(s[2*jj+1][0], s[2*jj+1][1], ph[2], pl[2]);
            pack_split2(s[2*jj+1][2], s[2*jj+1][3], ph[3], pl[3]);

            const uint32_t rowaddr = v_base + (uint32_t)(((jj * 16 + (lid & 15)) * QP) * 4);
            #pragma unroll
            for (int nt = 0; nt < 16; nt++) {
                uint32_t bh[2], bl[2];
                ldsm_x2_t(bh[0], bh[1], rowaddr + nt * 16);
                ldsm_x2_t(bl[0], bl[1], rowaddr + 256 + nt * 16);
                mma_bf16(o[nt], ph, bh);
                mma_bf16(o[nt], ph, bl);
                mma_bf16(o[nt], pl, bh);
            }
        }
    }

    const float i0 = 1.0f / l0, i1 = 1.0f / l1;
    #pragma unroll
    for (int nt = 0; nt < 16; nt++) {
        const int d = nt * 8 + 2 * t4;
        float2 a, b;
        a.x = o[nt][0] * i0; a.y = o[nt][1] * i0;
        b.x = o[nt][2] * i1; b.y = o[nt][3] * i1;
        *(float2*)&attn_out[(long)row0 * HID + h * HD + d] = a;
        *(float2*)&attn_out[(long)row1 * HID + h * HD + d] = b;
    }
}

// ---------------------------------------------------------------------------
extern "C" void kernel_launch(void* const* d_in, const int* in_sizes, int n_in,
                              void* d_out, int out_size)
{
    const float* x    = (const float*)d_in[0];
    const float* wqkv = (const float*)d_in[1];
    const float* bqkv = (const float*)d_in[2];
    const float* wo   = (const float*)d_in[3];
    const float* bo   = (const float*)d_in[4];
    float* out = (float*)d_out;

    float *qkv_buf, *attn_buf;
    cudaGetSymbolAddress((void**)&qkv_buf,  g_qkv);
    cudaGetSymbolAddress((void**)&attn_buf, g_attn);

    const int gemm_smem = 2 * GSTG * sizeof(uint32_t);     // 32768
    cudaFuncSetAttribute(gemm_f16s,
                         cudaFuncAttributeMaxDynamicSharedMemorySize, gemm_smem);

    const int attn_smem = 3 * 64 * QP * sizeof(uint32_t);  // 101376
    cudaFuncSetAttribute(mqa_flash_hmma,
                         cudaFuncAttributeMaxDynamicSharedMemorySize, attn_smem);

    // 1) QKV projection
    {
        dim3 grid(QKV_OUT / 128, S_LEN / 128);
        gemm_f16s<<<grid, 256, gemm_smem>>>(x, wqkv, bqkv, qkv_buf,
                                            S_LEN, QKV_OUT, HID);
    }
    // 2) attention
    {
        dim3 grid(S_LEN / 64, NH);
        mqa_flash_hmma<<<grid, 128, attn_smem>>>(qkv_buf, attn_buf);
    }
    // 3) output projection
    {
        dim3 grid(HID / 128, S_LEN / 128);
        gemm_f16s<<<grid, 256, gemm_smem>>>(attn_buf, wo, bo, out,
                                            S_LEN, HID, HID);
    }
}

// round 10
// speedup vs baseline: 1.5401x; 1.2970x over previous
#include <cuda_runtime.h>
#include <cuda_bf16.h>
#include <cuda_fp16.h>
#include <cstdint>

// Problem constants (B=1 fixed)
#define S_LEN   2048
#define HID     6144
#define QKV_OUT 6400   // HID + 2*128
#define NH      48
#define HD      128
#define KDIM    6144   // GEMM K (both projections)

// Scratch (no cudaMalloc allowed)
__device__ float  g_qkv [S_LEN * QKV_OUT];
__device__ float  g_attn[S_LEN * HID];
__device__ __half g_wh  [QKV_OUT * HID];   // wqkv fp16
__device__ __half g_woh [HID * HID];       // wo fp16
__device__ __half g_ah  [S_LEN * HID];     // activation hi plane
__device__ __half g_al  [S_LEN * HID];     // activation lo plane

// ---------------------------------------------------------------------------
// helpers
// ---------------------------------------------------------------------------
__device__ __forceinline__ uint32_t smem_u32(const void* p) {
    uint32_t a;
    asm("{ .reg .u64 t; cvta.to.shared.u64 t, %1; cvt.u32.u64 %0, t; }"
        : "=r"(a) : "l"(p));
    return a;
}

__device__ __forceinline__ void cp16(uint32_t dst, const void* src) {
    asm volatile("cp.async.cg.shared.global [%0], [%1], 16;"
                 :: "r"(dst), "l"(src) : "memory");
}
#define CP_COMMIT() asm volatile("cp.async.commit_group;" ::: "memory")
#define CP_WAIT1()  asm volatile("cp.async.wait_group 1;" ::: "memory")

__device__ __forceinline__ void mma_bf16(float* d, const uint32_t* a, const uint32_t* b) {
    asm volatile(
        "mma.sync.aligned.m16n8k16.row.col.f32.bf16.bf16.f32 "
        "{%0,%1,%2,%3}, {%4,%5,%6,%7}, {%8,%9}, {%0,%1,%2,%3};"
        : "+f"(d[0]), "+f"(d[1]), "+f"(d[2]), "+f"(d[3])
        : "r"(a[0]), "r"(a[1]), "r"(a[2]), "r"(a[3]), "r"(b[0]), "r"(b[1]));
}
__device__ __forceinline__ void mma_f16(float* d, const uint32_t* a, const uint32_t* b) {
    asm volatile(
        "mma.sync.aligned.m16n8k16.row.col.f32.f16.f16.f32 "
        "{%0,%1,%2,%3}, {%4,%5,%6,%7}, {%8,%9}, {%0,%1,%2,%3};"
        : "+f"(d[0]), "+f"(d[1]), "+f"(d[2]), "+f"(d[3])
        : "r"(a[0]), "r"(a[1]), "r"(a[2]), "r"(a[3]), "r"(b[0]), "r"(b[1]));
}

__device__ __forceinline__ void ldsm_x4(uint32_t* r, uint32_t addr) {
    asm volatile("ldmatrix.sync.aligned.m8n8.x4.shared.b16 {%0,%1,%2,%3}, [%4];"
                 : "=r"(r[0]), "=r"(r[1]), "=r"(r[2]), "=r"(r[3]) : "r"(addr));
}
__device__ __forceinline__ void ldsm_x2(uint32_t* r, uint32_t addr) {
    asm volatile("ldmatrix.sync.aligned.m8n8.x2.shared.b16 {%0,%1}, [%2];"
                 : "=r"(r[0]), "=r"(r[1]) : "r"(addr));
}
__device__ __forceinline__ void ldsm_x2_t(uint32_t& r0, uint32_t& r1, uint32_t addr) {
    asm volatile("ldmatrix.sync.aligned.m8n8.x2.trans.shared.b16 {%0,%1}, [%2];"
                 : "=r"(r0), "=r"(r1) : "r"(addr));
}

// ---- bf16 split helpers (attention) ----
__device__ __forceinline__ void pack_split2(float x, float y, uint32_t& hi, uint32_t& lo) {
    __nv_bfloat162 h = __floats2bfloat162_rn(x, y);
    float2 hf = __bfloat1622float2(h);
    __nv_bfloat162 l = __floats2bfloat162_rn(x - hf.x, y - hf.y);
    hi = *reinterpret_cast<uint32_t*>(&h);
    lo = *reinterpret_cast<uint32_t*>(&l);
}
__device__ __forceinline__ void split16(const float* src, uint32_t* hi, uint32_t* lo,
                                        float scale) {
    #pragma unroll
    for (int i = 0; i < 4; i++) {
        float4 f = *(const float4*)(src + i * 4);
        f.x *= scale; f.y *= scale; f.z *= scale; f.w *= scale;
        uint32_t h0, l0, h1, l1;
        pack_split2(f.x, f.y, h0, l0);
        pack_split2(f.z, f.w, h1, l1);
        hi[i * 2] = h0; hi[i * 2 + 1] = h1;
        lo[i * 2] = l0; lo[i * 2 + 1] = l1;
    }
}

// ---------------------------------------------------------------------------
// conversion kernels (run once per launch)
// ---------------------------------------------------------------------------
__global__ void __launch_bounds__(256) f32_to_f16_k(const float* __restrict__ in,
                                                    __half* __restrict__ out, int n4) {
    const int i = blockIdx.x * 256 + threadIdx.x;
    if (i < n4) {
        float4 f = ((const float4*)in)[i];
        __half2 a = __floats2half2_rn(f.x, f.y);
        __half2 b = __floats2half2_rn(f.z, f.w);
        uint32_t u0 = *reinterpret_cast<uint32_t*>(&a);
        uint32_t u1 = *reinterpret_cast<uint32_t*>(&b);
        ((uint2*)out)[i] = make_uint2(u0, u1);
    }
}

__global__ void __launch_bounds__(256) f32_split_f16_k(const float* __restrict__ in,
                                                       __half* __restrict__ hi,
                                                       __half* __restrict__ lo, int n4) {
    const int i = blockIdx.x * 256 + threadIdx.x;
    if (i < n4) {
        float4 f = ((const float4*)in)[i];
        __half2 h0 = __floats2half2_rn(f.x, f.y);
        __half2 h1 = __floats2half2_rn(f.z, f.w);
        float2 f0 = __half22float2(h0), f1 = __half22float2(h1);
        __half2 l0 = __floats2half2_rn(f.x - f0.x, f.y - f0.y);
        __half2 l1 = __floats2half2_rn(f.z - f1.x, f.w - f1.y);
        ((uint2*)hi)[i] = make_uint2(*reinterpret_cast<uint32_t*>(&h0),
                                     *reinterpret_cast<uint32_t*>(&h1));
        ((uint2*)lo)[i] = make_uint2(*reinterpret_cast<uint32_t*>(&l0),
                                     *reinterpret_cast<uint32_t*>(&l1));
    }
}

// ---------------------------------------------------------------------------
// fp16 async GEMM: C[M,N] = (Ah+Al)[M,K] * Bh[N,K]^T + bias[N]  (K=6144)
// CTA 128x128, BK=32, 256 threads, 8 warps (2x4), warp tile 64x32.
// 3-stage cp.async ring. Tile pitch 80B (16 u32 data + 4 pad): ldsm phases
// conflict-free ((5r+2ks) mod 8 distinct). 2 CTAs/SM.
// ---------------------------------------------------------------------------
#define TILE_B 10240                // 128 rows * 80B
#define STG_B  (3 * TILE_B)         // Ah + Al + B per stage (30720B)
#define NSTG   (KDIM / 32)          // 192

__global__ void __launch_bounds__(256, 2) gemm_f16a(
    const __half* __restrict__ Ah, const __half* __restrict__ Al,
    const __half* __restrict__ Bh,
    const float* __restrict__ bias, float* __restrict__ C, int N)
{
    extern __shared__ char gsm[];
    const uint32_t smb = smem_u32(gsm);

    const int tid = threadIdx.x;
    const int wid = tid >> 5, lid = tid & 31;
    const int g   = lid >> 2;
    const int t4  = lid & 3;
    const int wr  = wid >> 2;       // 0..1 (M)
    const int wc  = wid & 3;        // 0..3 (N)

    const int bm = blockIdx.y * 128, bn = blockIdx.x * 128;

    // cp.async loader: 2 threads per row; each thread copies 32B (2 chunks)
    // per tile per stage.
    const int lrow = tid >> 1;
    const int lel  = (tid & 1) * 16;          // fp16 element offset in the 32-wide slab
    const __half* Ahg = Ah + (long)(bm + lrow) * KDIM + lel;
    const __half* Alg = Al + (long)(bm + lrow) * KDIM + lel;
    const __half* Bg  = Bh + (long)(bn + lrow) * KDIM + lel;
    const uint32_t sdst = smb + (uint32_t)(lrow * 80 + lel * 2);

    // ldsm lane base addresses (bytes within a tile)
    const uint32_t a_row = (uint32_t)((wr * 64 + (lid & 15)) * 80 + (lid >> 4) * 16);
    const uint32_t b_row = (uint32_t)((wc * 32 + (lid & 7)) * 80 + ((lid >> 3) & 1) * 16);

    float acc[4][4][4];
    #pragma unroll
    for (int i = 0; i < 4; i++)
        #pragma unroll
        for (int j = 0; j < 4; j++)
            #pragma unroll
            for (int k = 0; k < 4; k++) acc[i][j][k] = 0.0f;

    // prologue: issue stages 0 and 1
    #pragma unroll
    for (int s = 0; s < 2; s++) {
        const uint32_t sb = sdst + s * STG_B;
        const long go = (long)s * 32;
        cp16(sb,               Ahg + go);  cp16(sb + 16,               Ahg + go + 8);
        cp16(sb + TILE_B,      Alg + go);  cp16(sb + TILE_B + 16,      Alg + go + 8);
        cp16(sb + 2 * TILE_B,  Bg  + go);  cp16(sb + 2 * TILE_B + 16,  Bg  + go + 8);
        CP_COMMIT();
    }

    int slot = 0;
    for (int s = 0; s < NSTG; s++) {
        CP_WAIT1();          // stage s resident
        __syncthreads();     // all threads agree; slot (s+2)%3's old readers done

        // issue stage s+2 (overlaps compute below)
        if (s + 2 < NSTG) {
            const int wslot = (slot + 2 >= 3) ? slot - 1 : slot + 2;
            const uint32_t sb = sdst + wslot * STG_B;
            const long go = (long)(s + 2) * 32;
            cp16(sb,               Ahg + go);  cp16(sb + 16,               Ahg + go + 8);
            cp16(sb + TILE_B,      Alg + go);  cp16(sb + TILE_B + 16,      Alg + go + 8);
            cp16(sb + 2 * TILE_B,  Bg  + go);  cp16(sb + 2 * TILE_B + 16,  Bg  + go + 8);
        }
        CP_COMMIT();         // empty groups at tail keep the accounting uniform

        // compute stage s from slot
        const uint32_t abase = smb + slot * STG_B + a_row;
        const uint32_t lbase = abase + TILE_B;
        const uint32_t bbase = smb + slot * STG_B + 2 * TILE_B + b_row;

        #pragma unroll
        for (int ks = 0; ks < 2; ks++) {
            uint32_t ah[4][4], al[4][4];
            #pragma unroll
            for (int mt = 0; mt < 4; mt++) {
                ldsm_x4(ah[mt], abase + ks * 32 + mt * (16 * 80));
                ldsm_x4(al[mt], lbase + ks * 32 + mt * (16 * 80));
            }
            #pragma unroll
            for (int nt = 0; nt < 4; nt++) {
                uint32_t bh[2];
                ldsm_x2(bh, bbase + ks * 32 + nt * (8 * 80));
                #pragma unroll
                for (int mt = 0; mt < 4; mt++) mma_f16(acc[mt][nt], ah[mt], bh);
                #pragma unroll
                for (int mt = 0; mt < 4; mt++) mma_f16(acc[mt][nt], al[mt], bh);
            }
        }

        slot = (slot + 1 == 3) ? 0 : slot + 1;
    }

    // epilogue
    #pragma unroll
    for (int mt = 0; mt < 4; mt++) {
        const int row = bm + wr * 64 + mt * 16 + g;
        #pragma unroll
        for (int nt = 0; nt < 4; nt++) {
            const int col = bn + wc * 32 + nt * 8 + t4 * 2;
            const float b0 = bias[col], b1 = bias[col + 1];
            float2 lo, hi;
            lo.x = acc[mt][nt][0] + b0; lo.y = acc[mt][nt][1] + b1;
            hi.x = acc[mt][nt][2] + b0; hi.y = acc[mt][nt][3] + b1;
            *(float2*)&C[(long)row * N + col]       = lo;
            *(float2*)&C[(long)(row + 8) * N + col] = hi;
        }
    }
}

// ---------------------------------------------------------------------------
// MQA causal flash attention, bf16-split HMMA (R6 version, measured best).
// ---------------------------------------------------------------------------
#define QP 132

__global__ void __launch_bounds__(128) mqa_flash_hmma(
    const float* __restrict__ qkv, float* __restrict__ attn_out)
{
    extern __shared__ uint32_t asm_[];
    uint32_t* q_s = asm_;
    uint32_t* k_s = q_s + 64 * QP;
    uint32_t* v_s = k_s + 64 * QP;

    const int h  = blockIdx.y;
    const int bq = blockIdx.x;
    const int q0 = bq * 64;
    const int tid = threadIdx.x;
    const int wid = tid >> 5, lid = tid & 31;
    const int g = lid >> 2, t4 = lid & 3;

    const uint32_t v_base = smem_u32(v_s);

    const int lr  = tid >> 1;
    const int lc0 = (tid & 1) * 16;

    {
        const float* src = qkv + (long)(q0 + lr) * QKV_OUT + h * HD;
        uint32_t* dst = q_s + lr * QP;
        #pragma unroll
        for (int jj = 0; jj < 4; jj++) {
            const int c16 = lc0 + 32 * jj;
            split16(src + c16, dst + (c16 >> 1), dst + (c16 >> 1) + 64,
                    0.08838834764831845f);
        }
    }

    float o[16][4];
    #pragma unroll
    for (int i = 0; i < 16; i++)
        #pragma unroll
        for (int j = 0; j < 4; j++) o[i][j] = 0.0f;
    float m0 = -1e30f, m1 = -1e30f, l0 = 0.0f, l1 = 0.0f;

    const int row0 = q0 + wid * 16 + g;
    const int row1 = row0 + 8;

    for (int kt = 0; kt <= bq; kt++) {
        __syncthreads();
        {
            const float* kp = qkv + (long)(kt * 64 + lr) * QKV_OUT + HID;
            uint32_t* kd = k_s + lr * QP;
            uint32_t* vd = v_s + lr * QP;
            #pragma unroll
            for (int jj = 0; jj < 4; jj++) {
                const int c16 = lc0 + 32 * jj;
                split16(kp + c16,      kd + (c16 >> 1), kd + (c16 >> 1) + 64, 1.0f);
                split16(kp + HD + c16, vd + (c16 >> 1), vd + (c16 >> 1) + 64, 1.0f);
            }
        }
        __syncthreads();

        float s[8][4];
        #pragma unroll
        for (int nt = 0; nt < 8; nt++)
            #pragma unroll
            for (int j = 0; j < 4; j++) s[nt][j] = 0.0f;

        const uint32_t* qb = q_s + (wid * 16) * QP;
        #pragma unroll
        for (int ks = 0; ks < 8; ks++) {
            uint32_t ah[4], al[4];
            const int ro = g * QP + ks * 8 + t4;
            ah[0] = qb[ro];          ah[1] = qb[ro + 8 * QP];
            ah[2] = qb[ro + 4];      ah[3] = qb[ro + 8 * QP + 4];
            al[0] = qb[ro + 64];     al[1] = qb[ro + 8 * QP + 64];
            al[2] = qb[ro + 68];     al[3] = qb[ro + 8 * QP + 68];
            #pragma unroll
            for (int nt = 0; nt < 8; nt++) {
                const int rb = (nt * 8 + g) * QP + ks * 8 + t4;
                uint32_t bh[2] = { k_s[rb],      k_s[rb + 4]  };
                uint32_t bl[2] = { k_s[rb + 64], k_s[rb + 68] };
                mma_bf16(s[nt], ah, bh);
                mma_bf16(s[nt], ah, bl);
                mma_bf16(s[nt], al, bh);
            }
        }

        if (kt == bq) {
            #pragma unroll
            for (int nt = 0; nt < 8; nt++) {
                const int col = kt * 64 + nt * 8 + 2 * t4;
                if (col     > row0) s[nt][0] = -1e30f;
                if (col + 1 > row0) s[nt][1] = -1e30f;
                if (col     > row1) s[nt][2] = -1e30f;
                if (col + 1 > row1) s[nt][3] = -1e30f;
            }
        }

        float mt0 = -1e30f, mt1 = -1e30f;
        #pragma unroll
        for (int nt = 0; nt < 8; nt++) {
            mt0 = fmaxf(mt0, fmaxf(s[nt][0], s[nt][1]));
            mt1 = fmaxf(mt1, fmaxf(s[nt][2], s[nt][3]));
        }
        mt0 = fmaxf(mt0, __shfl_xor_sync(0xffffffffu, mt0, 1));
        mt0 = fmaxf(mt0, __shfl_xor_sync(0xffffffffu, mt0, 2));
        mt1 = fmaxf(mt1, __shfl_xor_sync(0xffffffffu, mt1, 1));
        mt1 = fmaxf(mt1, __shfl_xor_sync(0xffffffffu, mt1, 2));

        const float mn0 = fmaxf(m0, mt0), mn1 = fmaxf(m1, mt1);
        const float al0 = __expf(m0 - mn0), al1 = __expf(m1 - mn1);

        float ps0 = 0.0f, ps1 = 0.0f;
        #pragma unroll
        for (int nt = 0; nt < 8; nt++) {
            s[nt][0] = __expf(s[nt][0] - mn0);
            s[nt][1] = __expf(s[nt][1] - mn0);
            s[nt][2] = __expf(s[nt][2] - mn1);
            s[nt][3] = __expf(s[nt][3] - mn1);
            ps0 += s[nt][0] + s[nt][1];
            ps1 += s[nt][2] + s[nt][3];
        }
        ps0 += __shfl_xor_sync(0xffffffffu, ps0, 1);
        ps0 += __shfl_xor_sync(0xffffffffu, ps0, 2);
        ps1 += __shfl_xor_sync(0xffffffffu, ps1, 1);
        ps1 += __shfl_xor_sync(0xffffffffu, ps1, 2);
        l0 = l0 * al0 + ps0; m0 = mn0;
        l1 = l1 * al1 + ps1; m1 = mn1;

        #pragma unroll
        for (int nt = 0; nt < 16; nt++) {
            o[nt][0] *= al0; o[nt][1] *= al0;
            o[nt][2] *= al1; o[nt][3] *= al1;
        }

        #pragma unroll
        for (int jj = 0; jj < 4; jj++) {
            uint32_t ph[4], pl[4];
            pack_split2(s[2*jj][0],   s[2*jj][1],   ph[0], pl[0]);
            pack_split2(s[2*jj][2],   s[2*jj][3],   ph[1], pl[1]);
            pack_split2(s[2*jj+1][0], s[2*jj+1][1], ph[2], pl[2]);
            pack_split2(s[2*jj+1][2], s[2*jj+1][3], ph[3], pl[3]);

            const uint32_t rowaddr = v_base + (uint32_t)(((jj * 16 + (lid & 15)) * QP) * 4);
            #pragma unroll
            for (int nt = 0; nt < 16; nt++) {
                uint32_t bh[2], bl[2];
                ldsm_x2_t(bh[0], bh[1], rowaddr + nt * 16);
                ldsm_x2_t(bl[0], bl[1], rowaddr + 256 + nt * 16);
                mma_bf16(o[nt], ph, bh);
                mma_bf16(o[nt], ph, bl);
                mma_bf16(o[nt], pl, bh);
            }
        }
    }

    const float i0 = 1.0f / l0, i1 = 1.0f / l1;
    #pragma unroll
    for (int nt = 0; nt < 16; nt++) {
        const int d = nt * 8 + 2 * t4;
        float2 a, b;
        a.x = o[nt][0] * i0; a.y = o[nt][1] * i0;
        b.x = o[nt][2] * i1; b.y = o[nt][3] * i1;
        *(float2*)&attn_out[(long)row0 * HID + h * HD + d] = a;
        *(float2*)&attn_out[(long)row1 * HID + h * HD + d] = b;
    }
}

// ---------------------------------------------------------------------------
extern "C" void kernel_launch(void* const* d_in, const int* in_sizes, int n_in,
                              void* d_out, int out_size)
{
    const float* x    = (const float*)d_in[0];
    const float* wqkv = (const float*)d_in[1];
    const float* bqkv = (const float*)d_in[2];
    const float* wo   = (const float*)d_in[3];
    const float* bo   = (const float*)d_in[4];
    float* out = (float*)d_out;

    float  *qkv_buf, *attn_buf;
    __half *wh, *woh, *ah, *al;
    cudaGetSymbolAddress((void**)&qkv_buf,  g_qkv);
    cudaGetSymbolAddress((void**)&attn_buf, g_attn);
    cudaGetSymbolAddress((void**)&wh,  g_wh);
    cudaGetSymbolAddress((void**)&woh, g_woh);
    cudaGetSymbolAddress((void**)&ah,  g_ah);
    cudaGetSymbolAddress((void**)&al,  g_al);

    const int gemm_smem = 3 * STG_B;                       // 92160
    cudaFuncSetAttribute(gemm_f16a,
                         cudaFuncAttributeMaxDynamicSharedMemorySize, gemm_smem);
    const int attn_smem = 3 * 64 * QP * sizeof(uint32_t);  // 101376
    cudaFuncSetAttribute(mqa_flash_hmma,
                         cudaFuncAttributeMaxDynamicSharedMemorySize, attn_smem);

    // 0) conversions (weights + input activations)
    {
        int n4 = (QKV_OUT * HID) / 4;
        f32_to_f16_k<<<(n4 + 255) / 256, 256>>>(wqkv, wh, n4);
        n4 = (HID * HID) / 4;
        f32_to_f16_k<<<(n4 + 255) / 256, 256>>>(wo, woh, n4);
        n4 = (S_LEN * HID) / 4;
        f32_split_f16_k<<<(n4 + 255) / 256, 256>>>(x, ah, al, n4);
    }

    // 1) QKV projection
    {
        dim3 grid(QKV_OUT / 128, S_LEN / 128);
        gemm_f16a<<<grid, 256, gemm_smem>>>(ah, al, wh, bqkv, qkv_buf, QKV_OUT);
    }
    // 2) attention
    {
        dim3 grid(S_LEN / 64, NH);
        mqa_flash_hmma<<<grid, 128, attn_smem>>>(qkv_buf, attn_buf);
    }
    // 3) split attention output, then output projection
    {
        int n4 = (S_LEN * HID) / 4;
        f32_split_f16_k<<<(n4 + 255) / 256, 256>>>(attn_buf, ah, al, n4);
        dim3 grid(HID / 128, S_LEN / 128);
        gemm_f16a<<<grid, 256, gemm_smem>>>(ah, al, woh, bo, out, HID);
    }
}

// round 11
// speedup vs baseline: 2.1449x; 1.3927x over previous
#include <cuda_runtime.h>
#include <cuda_bf16.h>
#include <cuda_fp16.h>
#include <cstdint>

// Problem constants (B=1 fixed)
#define S_LEN   2048
#define HID     6144
#define QKV_OUT 6400   // HID + 2*128
#define NH      48
#define HD      128
#define KDIM    6144   // GEMM K (both projections)

// Scratch (no cudaMalloc allowed)
__device__ float  g_qkv [S_LEN * QKV_OUT];
__device__ float  g_attn[S_LEN * HID];
__device__ __half g_wh  [QKV_OUT * HID];   // wqkv fp16
__device__ __half g_woh [HID * HID];       // wo fp16
__device__ __half g_ah  [S_LEN * HID];     // activation fp16

// ---------------------------------------------------------------------------
// helpers
// ---------------------------------------------------------------------------
__device__ __forceinline__ uint32_t smem_u32(const void* p) {
    uint32_t a;
    asm("{ .reg .u64 t; cvta.to.shared.u64 t, %1; cvt.u32.u64 %0, t; }"
        : "=r"(a) : "l"(p));
    return a;
}

__device__ __forceinline__ void cp16(uint32_t dst, const void* src) {
    asm volatile("cp.async.cg.shared.global [%0], [%1], 16;"
                 :: "r"(dst), "l"(src) : "memory");
}
#define CP_COMMIT() asm volatile("cp.async.commit_group;" ::: "memory")
#define CP_WAIT1()  asm volatile("cp.async.wait_group 1;" ::: "memory")

__device__ __forceinline__ void mma_bf16(float* d, const uint32_t* a, const uint32_t* b) {
    asm volatile(
        "mma.sync.aligned.m16n8k16.row.col.f32.bf16.bf16.f32 "
        "{%0,%1,%2,%3}, {%4,%5,%6,%7}, {%8,%9}, {%0,%1,%2,%3};"
        : "+f"(d[0]), "+f"(d[1]), "+f"(d[2]), "+f"(d[3])
        : "r"(a[0]), "r"(a[1]), "r"(a[2]), "r"(a[3]), "r"(b[0]), "r"(b[1]));
}
__device__ __forceinline__ void mma_f16(float* d, const uint32_t* a, const uint32_t* b) {
    asm volatile(
        "mma.sync.aligned.m16n8k16.row.col.f32.f16.f16.f32 "
        "{%0,%1,%2,%3}, {%4,%5,%6,%7}, {%8,%9}, {%0,%1,%2,%3};"
        : "+f"(d[0]), "+f"(d[1]), "+f"(d[2]), "+f"(d[3])
        : "r"(a[0]), "r"(a[1]), "r"(a[2]), "r"(a[3]), "r"(b[0]), "r"(b[1]));
}

__device__ __forceinline__ void ldsm_x4(uint32_t* r, uint32_t addr) {
    asm volatile("ldmatrix.sync.aligned.m8n8.x4.shared.b16 {%0,%1,%2,%3}, [%4];"
                 : "=r"(r[0]), "=r"(r[1]), "=r"(r[2]), "=r"(r[3]) : "r"(addr));
}
__device__ __forceinline__ void ldsm_x2(uint32_t* r, uint32_t addr) {
    asm volatile("ldmatrix.sync.aligned.m8n8.x2.shared.b16 {%0,%1}, [%2];"
                 : "=r"(r[0]), "=r"(r[1]) : "r"(addr));
}
__device__ __forceinline__ void ldsm_x2_t(uint32_t& r0, uint32_t& r1, uint32_t addr) {
    asm volatile("ldmatrix.sync.aligned.m8n8.x2.trans.shared.b16 {%0,%1}, [%2];"
                 : "=r"(r0), "=r"(r1) : "r"(addr));
}

// ---- bf16 split helpers (attention) ----
__device__ __forceinline__ void pack_split2(float x, float y, uint32_t& hi, uint32_t& lo) {
    __nv_bfloat162 h = __floats2bfloat162_rn(x, y);
    float2 hf = __bfloat1622float2(h);
    __nv_bfloat162 l = __floats2bfloat162_rn(x - hf.x, y - hf.y);
    hi = *reinterpret_cast<uint32_t*>(&h);
    lo = *reinterpret_cast<uint32_t*>(&l);
}
__device__ __forceinline__ void split16(const float* src, uint32_t* hi, uint32_t* lo,
                                        float scale) {
    #pragma unroll
    for (int i = 0; i < 4; i++) {
        float4 f = *(const float4*)(src + i * 4);
        f.x *= scale; f.y *= scale; f.z *= scale; f.w *= scale;
        uint32_t h0, l0, h1, l1;
        pack_split2(f.x, f.y, h0, l0);
        pack_split2(f.z, f.w, h1, l1);
        hi[i * 2] = h0; hi[i * 2 + 1] = h1;
        lo[i * 2] = l0; lo[i * 2 + 1] = l1;
    }
}

// ---------------------------------------------------------------------------
// conversion kernel (run once per launch per tensor)
// ---------------------------------------------------------------------------
__global__ void __launch_bounds__(256) f32_to_f16_k(const float* __restrict__ in,
                                                    __half* __restrict__ out, int n4) {
    const int i = blockIdx.x * 256 + threadIdx.x;
    if (i < n4) {
        float4 f = ((const float4*)in)[i];
        __half2 a = __floats2half2_rn(f.x, f.y);
        __half2 b = __floats2half2_rn(f.z, f.w);
        uint32_t u0 = *reinterpret_cast<uint32_t*>(&a);
        uint32_t u1 = *reinterpret_cast<uint32_t*>(&b);
        ((uint2*)out)[i] = make_uint2(u0, u1);
    }
}

// ---------------------------------------------------------------------------
// fp16 async GEMM: C[M,N] = Ah[M,K] * Bh[N,K]^T + bias[N]  (K=6144)
// CTA 128x128, BK=32, 256 threads, 8 warps (2x4), warp tile 64x32.
// 3-stage cp.async ring. Tile pitch 80B (64B data + 16B pad): ldsm phases
// conflict-free. 2 CTAs/SM.
// ---------------------------------------------------------------------------
#define TILE_B 10240                // 128 rows * 80B
#define STG_B  (2 * TILE_B)         // A + B per stage (20480B)
#define NSTG   (KDIM / 32)          // 192

__global__ void __launch_bounds__(256, 2) gemm_f16a(
    const __half* __restrict__ Ah, const __half* __restrict__ Bh,
    const float* __restrict__ bias, float* __restrict__ C, int N)
{
    extern __shared__ char gsm[];
    const uint32_t smb = smem_u32(gsm);

    const int tid = threadIdx.x;
    const int wid = tid >> 5, lid = tid & 31;
    const int g   = lid >> 2;
    const int t4  = lid & 3;
    const int wr  = wid >> 2;       // 0..1 (M)
    const int wc  = wid & 3;        // 0..3 (N)

    const int bm = blockIdx.y * 128, bn = blockIdx.x * 128;

    // cp.async loader: 2 threads per row; each thread copies 32B per tile.
    const int lrow = tid >> 1;
    const int lel  = (tid & 1) * 16;
    const __half* Ag = Ah + (long)(bm + lrow) * KDIM + lel;
    const __half* Bg = Bh + (long)(bn + lrow) * KDIM + lel;
    const uint32_t sdst = smb + (uint32_t)(lrow * 80 + lel * 2);

    // ldsm lane base addresses (bytes within a tile)
    const uint32_t a_row = (uint32_t)((wr * 64 + (lid & 15)) * 80 + (lid >> 4) * 16);
    const uint32_t b_row = (uint32_t)((wc * 32 + (lid & 7)) * 80 + ((lid >> 3) & 1) * 16);

    float acc[4][4][4];
    #pragma unroll
    for (int i = 0; i < 4; i++)
        #pragma unroll
        for (int j = 0; j < 4; j++)
            #pragma unroll
            for (int k = 0; k < 4; k++) acc[i][j][k] = 0.0f;

    // prologue: issue stages 0 and 1
    #pragma unroll
    for (int s = 0; s < 2; s++) {
        const uint32_t sb = sdst + s * STG_B;
        const long go = (long)s * 32;
        cp16(sb,          Ag + go);  cp16(sb + 16,          Ag + go + 8);
        cp16(sb + TILE_B, Bg + go);  cp16(sb + TILE_B + 16, Bg + go + 8);
        CP_COMMIT();
    }

    int slot = 0;
    for (int s = 0; s < NSTG; s++) {
        CP_WAIT1();
        __syncthreads();

        // issue stage s+2 (overlaps compute below)
        if (s + 2 < NSTG) {
            const int wslot = (slot + 2 >= 3) ? slot - 1 : slot + 2;
            const uint32_t sb = sdst + wslot * STG_B;
            const long go = (long)(s + 2) * 32;
            cp16(sb,          Ag + go);  cp16(sb + 16,          Ag + go + 8);
            cp16(sb + TILE_B, Bg + go);  cp16(sb + TILE_B + 16, Bg + go + 8);
        }
        CP_COMMIT();

        // compute stage s from slot
        const uint32_t abase = smb + slot * STG_B + a_row;
        const uint32_t bbase = smb + slot * STG_B + TILE_B + b_row;

        #pragma unroll
        for (int ks = 0; ks < 2; ks++) {
            uint32_t ah[4][4];
            #pragma unroll
            for (int mt = 0; mt < 4; mt++)
                ldsm_x4(ah[mt], abase + ks * 32 + mt * (16 * 80));
            #pragma unroll
            for (int nt = 0; nt < 4; nt++) {
                uint32_t bh[2];
                ldsm_x2(bh, bbase + ks * 32 + nt * (8 * 80));
                #pragma unroll
                for (int mt = 0; mt < 4; mt++) mma_f16(acc[mt][nt], ah[mt], bh);
            }
        }

        slot = (slot + 1 == 3) ? 0 : slot + 1;
    }

    // epilogue
    #pragma unroll
    for (int mt = 0; mt < 4; mt++) {
        const int row = bm + wr * 64 + mt * 16 + g;
        #pragma unroll
        for (int nt = 0; nt < 4; nt++) {
            const int col = bn + wc * 32 + nt * 8 + t4 * 2;
            const float b0 = bias[col], b1 = bias[col + 1];
            float2 lo, hi;
            lo.x = acc[mt][nt][0] + b0; lo.y = acc[mt][nt][1] + b1;
            hi.x = acc[mt][nt][2] + b0; hi.y = acc[mt][nt][3] + b1;
            *(float2*)&C[(long)row * N + col]       = lo;
            *(float2*)&C[(long)(row + 8) * N + col] = hi;
        }
    }
}

// ---------------------------------------------------------------------------
// MQA causal flash attention, bf16-split HMMA (unchanged — measured best).
// ---------------------------------------------------------------------------
#define QP 132

__global__ void __launch_bounds__(128) mqa_flash_hmma(
    const float* __restrict__ qkv, float* __restrict__ attn_out)
{
    extern __shared__ uint32_t asm_[];
    uint32_t* q_s = asm_;
    uint32_t* k_s = q_s + 64 * QP;
    uint32_t* v_s = k_s + 64 * QP;

    const int h  = blockIdx.y;
    const int bq = blockIdx.x;
    const int q0 = bq * 64;
    const int tid = threadIdx.x;
    const int wid = tid >> 5, lid = tid & 31;
    const int g = lid >> 2, t4 = lid & 3;

    const uint32_t v_base = smem_u32(v_s);

    const int lr  = tid >> 1;
    const int lc0 = (tid & 1) * 16;

    {
        const float* src = qkv + (long)(q0 + lr) * QKV_OUT + h * HD;
        uint32_t* dst = q_s + lr * QP;
        #pragma unroll
        for (int jj = 0; jj < 4; jj++) {
            const int c16 = lc0 + 32 * jj;
            split16(src + c16, dst + (c16 >> 1), dst + (c16 >> 1) + 64,
                    0.08838834764831845f);
        }
    }

    float o[16][4];
    #pragma unroll
    for (int i = 0; i < 16; i++)
        #pragma unroll
        for (int j = 0; j < 4; j++) o[i][j] = 0.0f;
    float m0 = -1e30f, m1 = -1e30f, l0 = 0.0f, l1 = 0.0f;

    const int row0 = q0 + wid * 16 + g;
    const int row1 = row0 + 8;

    for (int kt = 0; kt <= bq; kt++) {
        __syncthreads();
        {
            const float* kp = qkv + (long)(kt * 64 + lr) * QKV_OUT + HID;
            uint32_t* kd = k_s + lr * QP;
            uint32_t* vd = v_s + lr * QP;
            #pragma unroll
            for (int jj = 0; jj < 4; jj++) {
                const int c16 = lc0 + 32 * jj;
                split16(kp + c16,      kd + (c16 >> 1), kd + (c16 >> 1) + 64, 1.0f);
                split16(kp + HD + c16, vd + (c16 >> 1), vd + (c16 >> 1) + 64, 1.0f);
            }
        }
        __syncthreads();

        float s[8][4];
        #pragma unroll
        for (int nt = 0; nt < 8; nt++)
            #pragma unroll
            for (int j = 0; j < 4; j++) s[nt][j] = 0.0f;

        const uint32_t* qb = q_s + (wid * 16) * QP;
        #pragma unroll
        for (int ks = 0; ks < 8; ks++) {
            uint32_t ah[4], al[4];
            const int ro = g * QP + ks * 8 + t4;
            ah[0] = qb[ro];          ah[1] = qb[ro + 8 * QP];
            ah[2] = qb[ro + 4];      ah[3] = qb[ro + 8 * QP + 4];
            al[0] = qb[ro + 64];     al[1] = qb[ro + 8 * QP + 64];
            al[2] = qb[ro + 68];     al[3] = qb[ro + 8 * QP + 68];
            #pragma unroll
            for (int nt = 0; nt < 8; nt++) {
                const int rb = (nt * 8 + g) * QP + ks * 8 + t4;
                uint32_t bh[2] = { k_s[rb],      k_s[rb + 4]  };
                uint32_t bl[2] = { k_s[rb + 64], k_s[rb + 68] };
                mma_bf16(s[nt], ah, bh);
                mma_bf16(s[nt], ah, bl);
                mma_bf16(s[nt], al, bh);
            }
        }

        if (kt == bq) {
            #pragma unroll
            for (int nt = 0; nt < 8; nt++) {
                const int col = kt * 64 + nt * 8 + 2 * t4;
                if (col     > row0) s[nt][0] = -1e30f;
                if (col + 1 > row0) s[nt][1] = -1e30f;
                if (col     > row1) s[nt][2] = -1e30f;
                if (col + 1 > row1) s[nt][3] = -1e30f;
            }
        }

        float mt0 = -1e30f, mt1 = -1e30f;
        #pragma unroll
        for (int nt = 0; nt < 8; nt++) {
            mt0 = fmaxf(mt0, fmaxf(s[nt][0], s[nt][1]));
            mt1 = fmaxf(mt1, fmaxf(s[nt][2], s[nt][3]));
        }
        mt0 = fmaxf(mt0, __shfl_xor_sync(0xffffffffu, mt0, 1));
        mt0 = fmaxf(mt0, __shfl_xor_sync(0xffffffffu, mt0, 2));
        mt1 = fmaxf(mt1, __shfl_xor_sync(0xffffffffu, mt1, 1));
        mt1 = fmaxf(mt1, __shfl_xor_sync(0xffffffffu, mt1, 2));

        const float mn0 = fmaxf(m0, mt0), mn1 = fmaxf(m1, mt1);
        const float al0 = __expf(m0 - mn0), al1 = __expf(m1 - mn1);

        float ps0 = 0.0f, ps1 = 0.0f;
        #pragma unroll
        for (int nt = 0; nt < 8; nt++) {
            s[nt][0] = __expf(s[nt][0] - mn0);
            s[nt][1] = __expf(s[nt][1] - mn0);
            s[nt][2] = __expf(s[nt][2] - mn1);
            s[nt][3] = __expf(s[nt][3] - mn1);
            ps0 += s[nt][0] + s[nt][1];
            ps1 += s[nt][2] + s[nt][3];
        }
        ps0 += __shfl_xor_sync(0xffffffffu, ps0, 1);
        ps0 += __shfl_xor_sync(0xffffffffu, ps0, 2);
        ps1 += __shfl_xor_sync(0xffffffffu, ps1, 1);
        ps1 += __shfl_xor_sync(0xffffffffu, ps1, 2);
        l0 = l0 * al0 + ps0; m0 = mn0;
        l1 = l1 * al1 + ps1; m1 = mn1;

        #pragma unroll
        for (int nt = 0; nt < 16; nt++) {
            o[nt][0] *= al0; o[nt][1] *= al0;
            o[nt][2] *= al1; o[nt][3] *= al1;
        }

        #pragma unroll
        for (int jj = 0; jj < 4; jj++) {
            uint32_t ph[4], pl[4];
            pack_split2(s[2*jj][0],   s[2*jj][1],   ph[0], pl[0]);
            pack_split2(s[2*jj][2],   s[2*jj][3],   ph[1], pl[1]);
            pack_split2(s[2*jj+1][0], s[2*jj+1][1], ph[2], pl[2]);
            pack_split2(s[2*jj+1][2], s[2*jj+1][3], ph[3], pl[3]);

            const uint32_t rowaddr = v_base + (uint32_t)(((jj * 16 + (lid & 15)) * QP) * 4);
            #pragma unroll
            for (int nt = 0; nt < 16; nt++) {
                uint32_t bh[2], bl[2];
                ldsm_x2_t(bh[0], bh[1], rowaddr + nt * 16);
                ldsm_x2_t(bl[0], bl[1], rowaddr + 256 + nt * 16);
                mma_bf16(o[nt], ph, bh);
                mma_bf16(o[nt], ph, bl);
                mma_bf16(o[nt], pl, bh);
            }
        }
    }

    const float i0 = 1.0f / l0, i1 = 1.0f / l1;
    #pragma unroll
    for (int nt = 0; nt < 16; nt++) {
        const int d = nt * 8 + 2 * t4;
        float2 a, b;
        a.x = o[nt][0] * i0; a.y = o[nt][1] * i0;
        b.x = o[nt][2] * i1; b.y = o[nt][3] * i1;
        *(float2*)&attn_out[(long)row0 * HID + h * HD + d] = a;
        *(float2*)&attn_out[(long)row1 * HID + h * HD + d] = b;
    }
}

// ---------------------------------------------------------------------------
extern "C" void kernel_launch(void* const* d_in, const int* in_sizes, int n_in,
                              void* d_out, int out_size)
{
    const float* x    = (const float*)d_in[0];
    const float* wqkv = (const float*)d_in[1];
    const float* bqkv = (const float*)d_in[2];
    const float* wo   = (const float*)d_in[3];
    const float* bo   = (const float*)d_in[4];
    float* out = (float*)d_out;

    float  *qkv_buf, *attn_buf;
    __half *wh, *woh, *ah;
    cudaGetSymbolAddress((void**)&qkv_buf,  g_qkv);
    cudaGetSymbolAddress((void**)&attn_buf, g_attn);
    cudaGetSymbolAddress((void**)&wh,  g_wh);
    cudaGetSymbolAddress((void**)&woh, g_woh);
    cudaGetSymbolAddress((void**)&ah,  g_ah);

    const int gemm_smem = 3 * STG_B;                       // 61440
    cudaFuncSetAttribute(gemm_f16a,
                         cudaFuncAttributeMaxDynamicSharedMemorySize, gemm_smem);
    const int attn_smem = 3 * 64 * QP * sizeof(uint32_t);  // 101376
    cudaFuncSetAttribute(mqa_flash_hmma,
                         cudaFuncAttributeMaxDynamicSharedMemorySize, attn_smem);

    // 0) conversions (weights + input activations)
    {
        int n4 = (QKV_OUT * HID) / 4;
        f32_to_f16_k<<<(n4 + 255) / 256, 256>>>(wqkv, wh, n4);
        n4 = (HID * HID) / 4;
        f32_to_f16_k<<<(n4 + 255) / 256, 256>>>(wo, woh, n4);
        n4 = (S_LEN * HID) / 4;
        f32_to_f16_k<<<(n4 + 255) / 256, 256>>>(x, ah, n4);
    }

    // 1) QKV projection
    {
        dim3 grid(QKV_OUT / 128, S_LEN / 128);
        gemm_f16a<<<grid, 256, gemm_smem>>>(ah, wh, bqkv, qkv_buf, QKV_OUT);
    }
    // 2) attention
    {
        dim3 grid(S_LEN / 64, NH);
        mqa_flash_hmma<<<grid, 128, attn_smem>>>(qkv_buf, attn_buf);
    }
    // 3) convert attention output, then output projection
    {
        int n4 = (S_LEN * HID) / 4;
        f32_to_f16_k<<<(n4 + 255) / 256, 256>>>(attn_buf, ah, n4);
        dim3 grid(HID / 128, S_LEN / 128);
        gemm_f16a<<<grid, 256, gemm_smem>>>(ah, woh, bo, out, HID);
    }
}